// round 7
// baseline (speedup 1.0000x reference)
#include <cuda_runtime.h>

// PowerLinear:
//   c = colsum(R), rs = rowsum(R)
//   n_b == 0 : y_b = (c . x_b) * rs     (sum of chunk-local cxp * rs over ks)
//   n_b >= 1 : y_b = R @ ( d^{n_b} * c * x_b )
// Inputs: x [64,1024] f32, n [64] i32, diag [1024] f32, rot [1024,1024] f32
// Output: [64,1024] f32

#define BB 64
#define DD 1024
#define NP 128            // colsum partial count (prep grid)
#define KSPLIT 16
#define KCHUNK 64         // DD / KSPLIT
#define KC 16
#define NSTAGE 4          // KCHUNK / KC
#define PADB 68
#define PADW 68

typedef unsigned long long u64;

__device__ float g_cp[NP * DD];   // colsum partials [p][j]
__device__ float g_rs[DD];        // rowsums

__device__ __forceinline__ void redadd2(float* p, float a, float b)
{
    asm volatile("red.global.add.v2.f32 [%0], {%1, %2};"
                 :: "l"(p), "f"(a), "f"(b) : "memory");
}
__device__ __forceinline__ u64 pk2(float lo, float hi)
{
    u64 r;
    asm("mov.b64 %0, {%1,%2};" : "=l"(r) : "f"(lo), "f"(hi));
    return r;
}
__device__ __forceinline__ void upk2(u64 v, float& lo, float& hi)
{
    asm("mov.b64 {%0,%1}, %2;" : "=f"(lo), "=f"(hi) : "l"(v));
}
__device__ __forceinline__ void fma2(u64& d, u64 a, u64 b)
{
    asm("fma.rn.f32x2 %0, %1, %2, %0;" : "+l"(d) : "l"(a), "l"(b));
}

// ---------------------------------------------------------------------------
// K1: colsum partials (8 rows/block) + exact rowsums + zero out. grid 128x256.
// ---------------------------------------------------------------------------
__global__ __launch_bounds__(256) void prep_kernel(const float* __restrict__ R,
                                                   float* __restrict__ out)
{
    const int bid = blockIdx.x;
    const int tid = threadIdx.x;

    const float* rp = R + (bid * 8) * DD + tid * 4;
    float4 a = make_float4(0.f, 0.f, 0.f, 0.f);
    float rs[8];
#pragma unroll
    for (int r = 0; r < 8; r++) {
        float4 v = *(const float4*)(rp + r * DD);
        a.x += v.x; a.y += v.y; a.z += v.z; a.w += v.w;
        rs[r] = (v.x + v.y) + (v.z + v.w);
    }
    *(float4*)(g_cp + bid * DD + tid * 4) = a;

    __shared__ float srs[8][256];
#pragma unroll
    for (int r = 0; r < 8; r++) srs[r][tid] = rs[r];
    __syncthreads();
#pragma unroll
    for (int off = 128; off > 0; off >>= 1) {
        if (tid < off) {
#pragma unroll
            for (int r = 0; r < 8; r++) srs[r][tid] += srs[r][tid + off];
        }
        __syncthreads();
    }
    if (tid < 8) g_rs[bid * 8 + tid] = srs[tid][0];

    *(float2*)(out + bid * 512 + tid * 2) = make_float2(0.f, 0.f);
}

// ---------------------------------------------------------------------------
// K2: split-K GEMM with f32x2 packed FMAs.
// Grid 256 = 16 i-tiles x 16 k-chunks, 128 threads/block.
// Thread tile: 8 b x 4 i (i packed into u64 pairs). W pre-duplicated in smem.
// ---------------------------------------------------------------------------
__global__ __launch_bounds__(128, 4)
void gemm_kernel(const float* __restrict__ x,
                 const int*   __restrict__ n,
                 const float* __restrict__ diag,
                 const float* __restrict__ R,
                 float*       __restrict__ out)
{
    __shared__ __align__(16) u64   sWd[KCHUNK][PADW];   // (w,w) dup [k][b]
    __shared__ __align__(16) float sB[2][KC][PADB];     // R[k][i] transposed
    __shared__ float sm_cred[2][KCHUNK];
    __shared__ float sm_c[KCHUNK];
    __shared__ float sm_rs[64];
    __shared__ float sm_cxp[64];
    __shared__ int   sm_n0[64];

    const int bid = blockIdx.x;
    const int tid = threadIdx.x;
    const int it  = bid >> 4;           // 0..15
    const int ks  = bid & 15;           // 0..15
    const int i0  = it * 64;
    const int k0  = ks * KCHUNK;

    // ---- prologue: c chunk (2-way split over 128 partials) -----------------
    {
        const int col = tid & 63;
        const int ph  = tid >> 6;       // 0..1
        float s = 0.f;
#pragma unroll 16
        for (int p = ph * 64; p < ph * 64 + 64; p++)
            s += g_cp[p * DD + k0 + col];
        sm_cred[ph][col] = s;
    }
    __syncthreads();
    if (tid < 64)       sm_c[tid] = sm_cred[0][tid] + sm_cred[1][tid];
    else                sm_rs[tid - 64] = g_rs[i0 + (tid - 64)];
    __syncthreads();

    // ---- build duplicated W tile + chunk-local cxp -------------------------
    {
        const int wb   = tid >> 1;        // 0..63
        const int half = tid & 1;         // 32-k half
        const int nb   = n[wb];
        float cxp = 0.f;
#pragma unroll
        for (int m = 0; m < 8; m++) {
            const int kk = half * 32 + m * 4;
            float4 xv = *(const float4*)(x + wb * DD + k0 + kk);
            float4 dv = *(const float4*)(diag + k0 + kk);
            float xs[4] = {xv.x, xv.y, xv.z, xv.w};
            float ds[4] = {dv.x, dv.y, dv.z, dv.w};
#pragma unroll
            for (int c = 0; c < 4; c++) {
                const float cx = sm_c[kk + c] * xs[c];
                cxp += cx;
                float p = 1.f;
#pragma unroll
                for (int k = 0; k < 5; k++) p *= (k < nb) ? ds[c] : 1.f;
                const float w = (nb == 0) ? 0.f : cx * p;
                sWd[kk + c][wb] = pk2(w, w);
            }
        }
        cxp += __shfl_xor_sync(0xffffffffu, cxp, 1);
        if (half == 0) {
            sm_cxp[wb] = cxp;
            sm_n0[wb]  = (nb == 0);
        }
    }

    // ---- main loop: stream R, packed FMAs ----------------------------------
    const int tx = tid & 15;            // i quad
    const int ty = tid >> 4;            // b octet (0..7)
    const int i4 = tx * 4;
    const int b8 = ty * 8;
    const int li = tid >> 1;            // R loader row 0..63
    const int lk = (tid & 1) * 8;       // R loader k offset {0,8}

    u64 acc[8][2];
#pragma unroll
    for (int r = 0; r < 8; r++) { acc[r][0] = 0ull; acc[r][1] = 0ull; }

    const float* rptr = R + (i0 + li) * DD + k0 + lk;
    float4 ra0 = *(const float4*)(rptr);
    float4 ra1 = *(const float4*)(rptr + 4);
    __syncthreads();   // sWd / sm_* ready

    int buf = 0;
#pragma unroll
    for (int s = 0; s < NSTAGE; s++) {
        sB[buf][lk + 0][li] = ra0.x;
        sB[buf][lk + 1][li] = ra0.y;
        sB[buf][lk + 2][li] = ra0.z;
        sB[buf][lk + 3][li] = ra0.w;
        sB[buf][lk + 4][li] = ra1.x;
        sB[buf][lk + 5][li] = ra1.y;
        sB[buf][lk + 6][li] = ra1.z;
        sB[buf][lk + 7][li] = ra1.w;
        __syncthreads();

        if (s + 1 < NSTAGE) {
            ra0 = *(const float4*)(rptr + (s + 1) * KC);
            ra1 = *(const float4*)(rptr + (s + 1) * KC + 4);
        }

#pragma unroll
        for (int kk = 0; kk < KC; kk++) {
            const u64* wrow = &sWd[s * KC + kk][b8];
            ulonglong2 w01 = *(const ulonglong2*)(wrow);
            ulonglong2 w23 = *(const ulonglong2*)(wrow + 2);
            ulonglong2 w45 = *(const ulonglong2*)(wrow + 4);
            ulonglong2 w67 = *(const ulonglong2*)(wrow + 6);
            ulonglong2 rr  = *(const ulonglong2*)&sB[buf][kk][i4];
            fma2(acc[0][0], w01.x, rr.x); fma2(acc[0][1], w01.x, rr.y);
            fma2(acc[1][0], w01.y, rr.x); fma2(acc[1][1], w01.y, rr.y);
            fma2(acc[2][0], w23.x, rr.x); fma2(acc[2][1], w23.x, rr.y);
            fma2(acc[3][0], w23.y, rr.x); fma2(acc[3][1], w23.y, rr.y);
            fma2(acc[4][0], w45.x, rr.x); fma2(acc[4][1], w45.x, rr.y);
            fma2(acc[5][0], w45.y, rr.x); fma2(acc[5][1], w45.y, rr.y);
            fma2(acc[6][0], w67.x, rr.x); fma2(acc[6][1], w67.x, rr.y);
            fma2(acc[7][0], w67.y, rr.x); fma2(acc[7][1], w67.y, rr.y);
        }
        buf ^= 1;
    }

    // ---- epilogue: vector atomics + n==0 rank-1 term -----------------------
    const float rs0 = sm_rs[i4 + 0];
    const float rs1 = sm_rs[i4 + 1];
    const float rs2 = sm_rs[i4 + 2];
    const float rs3 = sm_rs[i4 + 3];
#pragma unroll
    for (int r = 0; r < 8; r++) {
        const int b = b8 + r;
        const float ex = sm_n0[b] ? sm_cxp[b] : 0.f;
        float v0, v1, v2, v3;
        upk2(acc[r][0], v0, v1);
        upk2(acc[r][1], v2, v3);
        float* po = out + b * DD + i0 + i4;
        redadd2(po,     v0 + ex * rs0, v1 + ex * rs1);
        redadd2(po + 2, v2 + ex * rs2, v3 + ex * rs3);
    }
}

// ---------------------------------------------------------------------------
extern "C" void kernel_launch(void* const* d_in, const int* in_sizes, int n_in,
                              void* d_out, int out_size)
{
    const float* x    = (const float*)d_in[0];
    const int*   nn   = (const int*)  d_in[1];
    const float* diag = (const float*)d_in[2];
    const float* rot  = (const float*)d_in[3];
    float* out = (float*)d_out;

    prep_kernel<<<NP, 256>>>(rot, out);
    gemm_kernel<<<256, 128>>>(x, nn, diag, rot, out);
}

// round 10
// speedup vs baseline: 1.1584x; 1.1584x over previous
#include <cuda_runtime.h>

// PowerLinear:
//   c = colsum(R), rs = rowsum(R)
//   n_b == 0 : y_b = (c . x_b) * rs     (sum of chunk-local cxp * rs over ks)
//   n_b >= 1 : y_b = R @ ( d^{n_b} * c * x_b )
// Inputs: x [64,1024] f32, n [64] i32, diag [1024] f32, rot [1024,1024] f32
// Output: [64,1024] f32

#define BB 64
#define DD 1024
#define NP 128            // colsum partial count (prep grid)
#define KSPLIT 16
#define KCHUNK 64         // DD / KSPLIT
#define PADB 68           // float pad (272B stride: 16B-aligned, conflict-free)
#define PADW 66           // u64 pad (528B stride: 16B-aligned)

#define SWD_BYTES (KCHUNK * PADW * 8)         // 33792
#define SB_BYTES  (KCHUNK * PADB * 4)         // 17408
#define SMEM_TOTAL (SWD_BYTES + SB_BYTES + 1024 /*cred*/ + 256 /*c*/ + \
                    256 /*rs*/ + 256 /*cxp*/ + 256 /*n0*/)   // 53248

typedef unsigned long long u64;

__device__ float g_cp[NP * DD];   // colsum partials [p][j]
__device__ float g_rs[DD];        // rowsums

__device__ __forceinline__ void redadd2(float* p, float a, float b)
{
    asm volatile("red.global.add.v2.f32 [%0], {%1, %2};"
                 :: "l"(p), "f"(a), "f"(b) : "memory");
}
__device__ __forceinline__ u64 pk2(float lo, float hi)
{
    u64 r;
    asm("mov.b64 %0, {%1,%2};" : "=l"(r) : "f"(lo), "f"(hi));
    return r;
}
__device__ __forceinline__ void upk2(u64 v, float& lo, float& hi)
{
    asm("mov.b64 {%0,%1}, %2;" : "=f"(lo), "=f"(hi) : "l"(v));
}
__device__ __forceinline__ void fma2(u64& d, u64 a, u64 b)
{
    asm("fma.rn.f32x2 %0, %1, %2, %0;" : "+l"(d) : "l"(a), "l"(b));
}

// ---------------------------------------------------------------------------
// K1: colsum partials (8 rows/block) + exact rowsums + zero out. grid 128x256.
// ---------------------------------------------------------------------------
__global__ __launch_bounds__(256) void prep_kernel(const float* __restrict__ R,
                                                   float* __restrict__ out)
{
    const int bid  = blockIdx.x;
    const int tid  = threadIdx.x;
    const int wid  = tid >> 5;
    const int lane = tid & 31;

    const float* rp = R + (bid * 8) * DD + tid * 4;
    float4 a = make_float4(0.f, 0.f, 0.f, 0.f);
    float rs[8];
#pragma unroll
    for (int r = 0; r < 8; r++) {
        float4 v = *(const float4*)(rp + r * DD);
        a.x += v.x; a.y += v.y; a.z += v.z; a.w += v.w;
        rs[r] = (v.x + v.y) + (v.z + v.w);
    }
    *(float4*)(g_cp + bid * DD + tid * 4) = a;

    __shared__ float srs[8][8];
#pragma unroll
    for (int r = 0; r < 8; r++) {
#pragma unroll
        for (int off = 16; off > 0; off >>= 1)
            rs[r] += __shfl_down_sync(0xffffffffu, rs[r], off);
    }
    if (lane == 0) {
#pragma unroll
        for (int r = 0; r < 8; r++) srs[r][wid] = rs[r];
    }
    __syncthreads();
    if (tid < 8) {
        float s = 0.f;
#pragma unroll
        for (int w = 0; w < 8; w++) s += srs[tid][w];
        g_rs[bid * 8 + tid] = s;
    }

    // zero output (64*1024 / 128 blocks = 512 floats per block)
    *(float2*)(out + bid * 512 + tid * 2) = make_float2(0.f, 0.f);
}

// ---------------------------------------------------------------------------
// K2: split-K GEMM, f32x2 packed FMAs at full occupancy (dynamic smem).
// Grid 256 = 16 i-tiles x 16 k-chunks, 256 threads, 2 blocks/SM.
// Thread tile: 4b x 4i (i packed as u64 pairs). W pre-duplicated in smem.
// Single-buffered full 64x64 R tile, one main sync.
// ---------------------------------------------------------------------------
__global__ __launch_bounds__(256, 2)
void gemm_kernel(const float* __restrict__ x,
                 const int*   __restrict__ n,
                 const float* __restrict__ diag,
                 const float* __restrict__ R,
                 float*       __restrict__ out)
{
    extern __shared__ __align__(16) char smem_raw[];
    u64   (*sWd)[PADW] = (u64 (*)[PADW])(smem_raw);                 // (w,w) dup [k][b]
    float (*sB)[PADB]  = (float (*)[PADB])(smem_raw + SWD_BYTES);   // R[k][i] transposed
    float (*sm_cred)[KCHUNK] =
        (float (*)[KCHUNK])(smem_raw + SWD_BYTES + SB_BYTES);       // [4][64]
    float* sm_c   = (float*)(smem_raw + SWD_BYTES + SB_BYTES + 1024);
    float* sm_rs  = sm_c + 64;
    float* sm_cxp = sm_rs + 64;
    int*   sm_n0  = (int*)(sm_cxp + 64);

    const int bid = blockIdx.x;
    const int tid = threadIdx.x;
    const int it  = bid >> 4;           // 0..15
    const int ks  = bid & 15;           // 0..15
    const int i0  = it * 64;
    const int k0  = ks * KCHUNK;

    // ---- issue R tile loads first (latency overlaps prologue) --------------
    const int li = tid >> 2;            // row 0..63
    const int lk = (tid & 3) * 4;       // k offset {0,4,8,12}
    const float* rptr = R + (i0 + li) * DD + k0 + lk;
    float4 ra0 = *(const float4*)(rptr);
    float4 ra1 = *(const float4*)(rptr + 16);
    float4 ra2 = *(const float4*)(rptr + 32);
    float4 ra3 = *(const float4*)(rptr + 48);

    // ---- prologue: c chunk (4-way split over 128 partials), rs tile --------
    {
        const int col = tid & 63;
        const int ph  = tid >> 6;       // 0..3
        float s = 0.f;
#pragma unroll 16
        for (int p = ph * 32; p < ph * 32 + 32; p++)
            s += g_cp[p * DD + k0 + col];
        sm_cred[ph][col] = s;
    }
    __syncthreads();
    if (tid < 64)
        sm_c[tid] = (sm_cred[0][tid] + sm_cred[1][tid]) +
                    (sm_cred[2][tid] + sm_cred[3][tid]);
    else if (tid < 128)
        sm_rs[tid - 64] = g_rs[i0 + (tid - 64)];
    __syncthreads();

    // ---- build duplicated W tile + chunk-local cxp -------------------------
    {
        const int wb = tid >> 2;          // b 0..63
        const int wq = (tid & 3) * 4;     // k quad base
        const int nb = n[wb];
        float cxp = 0.f;
#pragma unroll
        for (int m = 0; m < 4; m++) {
            const int kk = wq + 16 * m;
            float4 xv = *(const float4*)(x + wb * DD + k0 + kk);
            float4 dv = *(const float4*)(diag + k0 + kk);
            float xs[4] = {xv.x, xv.y, xv.z, xv.w};
            float ds[4] = {dv.x, dv.y, dv.z, dv.w};
#pragma unroll
            for (int c = 0; c < 4; c++) {
                const float cx = sm_c[kk + c] * xs[c];
                cxp += cx;
                float p = 1.f;
#pragma unroll
                for (int k = 0; k < 5; k++) p *= (k < nb) ? ds[c] : 1.f;
                const float w = (nb == 0) ? 0.f : cx * p;
                sWd[kk + c][wb] = pk2(w, w);
            }
        }
        cxp += __shfl_down_sync(0xffffffffu, cxp, 1, 4);
        cxp += __shfl_down_sync(0xffffffffu, cxp, 2, 4);
        if ((tid & 3) == 0) {
            sm_cxp[wb] = cxp;
            sm_n0[wb]  = (nb == 0);
        }
    }

    // ---- store R tile to smem (transposed), one sync -----------------------
    {
        float4 rv[4] = {ra0, ra1, ra2, ra3};
#pragma unroll
        for (int s = 0; s < 4; s++) {
            const int kr = s * 16 + lk;
            sB[kr + 0][li] = rv[s].x;
            sB[kr + 1][li] = rv[s].y;
            sB[kr + 2][li] = rv[s].z;
            sB[kr + 3][li] = rv[s].w;
        }
    }
    __syncthreads();

    // ---- main loop: 64 k iterations, 8 FFMA2 each --------------------------
    const int tx = tid & 15;            // i quad
    const int ty = tid >> 4;            // b quad
    const int i4 = tx * 4;
    const int b4 = ty * 4;

    u64 acc[4][2];
#pragma unroll
    for (int r = 0; r < 4; r++) { acc[r][0] = 0ull; acc[r][1] = 0ull; }

#pragma unroll 16
    for (int kk = 0; kk < KCHUNK; kk++) {
        ulonglong2 w01 = *(const ulonglong2*)&sWd[kk][b4];
        ulonglong2 w23 = *(const ulonglong2*)&sWd[kk][b4 + 2];
        ulonglong2 rr  = *(const ulonglong2*)&sB[kk][i4];
        fma2(acc[0][0], w01.x, rr.x); fma2(acc[0][1], w01.x, rr.y);
        fma2(acc[1][0], w01.y, rr.x); fma2(acc[1][1], w01.y, rr.y);
        fma2(acc[2][0], w23.x, rr.x); fma2(acc[2][1], w23.x, rr.y);
        fma2(acc[3][0], w23.y, rr.x); fma2(acc[3][1], w23.y, rr.y);
    }

    // ---- epilogue: vector atomics + n==0 rank-1 term -----------------------
    const float rs0 = sm_rs[i4 + 0];
    const float rs1 = sm_rs[i4 + 1];
    const float rs2 = sm_rs[i4 + 2];
    const float rs3 = sm_rs[i4 + 3];
#pragma unroll
    for (int r = 0; r < 4; r++) {
        const int b = b4 + r;
        const float ex = sm_n0[b] ? sm_cxp[b] : 0.f;
        float v0, v1, v2, v3;
        upk2(acc[r][0], v0, v1);
        upk2(acc[r][1], v2, v3);
        float* po = out + b * DD + i0 + i4;
        redadd2(po,     v0 + ex * rs0, v1 + ex * rs1);
        redadd2(po + 2, v2 + ex * rs2, v3 + ex * rs3);
    }
}

// ---------------------------------------------------------------------------
extern "C" void kernel_launch(void* const* d_in, const int* in_sizes, int n_in,
                              void* d_out, int out_size)
{
    const float* x    = (const float*)d_in[0];
    const int*   nn   = (const int*)  d_in[1];
    const float* diag = (const float*)d_in[2];
    const float* rot  = (const float*)d_in[3];
    float* out = (float*)d_out;

    // host-side attribute set: not an allocation, idempotent, capture-safe
    cudaFuncSetAttribute(gemm_kernel,
                         cudaFuncAttributeMaxDynamicSharedMemorySize,
                         SMEM_TOTAL);

    prep_kernel<<<NP, 256>>>(rot, out);
    gemm_kernel<<<256, 256, SMEM_TOTAL>>>(x, nn, diag, rot, out);
}